// round 2
// baseline (speedup 1.0000x reference)
#include <cuda_runtime.h>
#include <cstdint>

#define BATCH_N   16384
#define FEAT      27          // combined features (1 dense + 26 sparse)
#define EMB       128
#define S_PER_CTA 32          // samples per CTA
#define NTHREADS  320         // 10 warps = 10 upper tiles
#define TDIM      7           // register tile dim (pad 27 -> 28 rows)
#define RSTRIDE   29          // per-sample row stride in smem quads (odd -> conflict-free)
#define VP        929         // quads per k-quad plane (32*29=928 -> 929, odd)
#define KC        8           // k elements per chunk
#define NCHUNK    (EMB/KC)    // 16
#define QPC       (KC/4)      // 2 float4-quads per chunk
#define NPAIR     351         // upper-triangle pair count
#define OUTW      479         // 128 + 351
#define SMEM_BYTES (2 * QPC * VP * 16)   // 59,456 B (double buffered)

static __device__ const int TI_TAB[10] = {0,0,0,0,1,1,1,2,2,3};
static __device__ const int TJ_TAB[10] = {0,1,2,3,1,2,3,2,3,3};

__device__ __forceinline__ unsigned long long ffma2(unsigned long long a,
                                                    unsigned long long b,
                                                    unsigned long long c) {
    unsigned long long d;
    asm("fma.rn.f32x2 %0, %1, %2, %3;" : "=l"(d) : "l"(a), "l"(b), "l"(c));
    return d;
}

__device__ __forceinline__ void cp_async16(uint32_t smem_addr, const void* gmem) {
    asm volatile("cp.async.cg.shared.global [%0], [%1], 16;" :: "r"(smem_addr), "l"(gmem));
}
__device__ __forceinline__ void cp_commit() {
    asm volatile("cp.async.commit_group;");
}
template <int N>
__device__ __forceinline__ void cp_wait() {
    asm volatile("cp.async.wait_group %0;" :: "n"(N));
}

__global__ void __launch_bounds__(NTHREADS, 1)
interaction_kernel(const float* __restrict__ dense,
                   const float* __restrict__ sparse,
                   float* __restrict__ out) {
    extern __shared__ ulonglong2 smem[];   // [2 buf][QPC][VP] of 16B quads

    const int tid  = threadIdx.x;
    const int warp = tid >> 5;
    const int lane = tid & 31;
    const int b0   = blockIdx.x * S_PER_CTA;

    const uint32_t smem_base = (uint32_t)__cvta_generic_to_shared(smem);

    // chunk loader: stage k-slice [c*KC, c*KC+KC) of all 27 rows x 32 samples
    auto issue_chunk = [&](int c, int bf) {
        const int kf = c * KC;                     // float offset of chunk
#pragma unroll
        for (int it = 0; it < 6; ++it) {
            int idx = tid + it * NTHREADS;
            if (idx < FEAT * S_PER_CTA * QPC) {    // 1728 quads
                int kq = idx & (QPC - 1);
                int rf = idx >> 1;                 // 0..863
                int s  = rf / FEAT;
                int f  = rf - s * FEAT;
                int b  = b0 + s;
                const float* src;
                if (f == 0)
                    src = dense + (size_t)b * EMB + kf + kq * 4;
                else
                    src = sparse + ((size_t)b * (FEAT - 1) + (f - 1)) * EMB + kf + kq * 4;
                uint32_t dst = smem_base +
                    (uint32_t)(((bf * QPC + kq) * VP + s * RSTRIDE + f) * 16);
                cp_async16(dst, src);
            }
        }
    };

    // ---- kick off first K-chunk immediately (overlaps passthrough below) ----
    issue_chunk(0, 0);
    cp_commit();

    // ---- zero the padding row (row 27) in both buffers, both quads ----
    for (int idx = tid; idx < S_PER_CTA * 2 * QPC; idx += NTHREADS) {
        int s    = idx & (S_PER_CTA - 1);
        int rest = idx >> 5;            // 0..3
        int kq   = rest & (QPC - 1);
        int bf   = rest >> 1;
        smem[(bf * QPC + kq) * VP + s * RSTRIDE + FEAT] = make_ulonglong2(0ULL, 0ULL);
    }

    // ---- dense passthrough: out[b][0:128] = dense[b][:] ----
    for (int idx = tid; idx < S_PER_CTA * EMB; idx += NTHREADS) {
        int s = idx >> 7;
        int d = idx & (EMB - 1);
        out[(size_t)(b0 + s) * OUTW + d] = dense[(size_t)(b0 + s) * EMB + d];
    }

    const int ti = TI_TAB[warp];
    const int tj = TJ_TAB[warp];

    unsigned long long acc[TDIM][TDIM];
#pragma unroll
    for (int r = 0; r < TDIM; ++r)
#pragma unroll
        for (int c = 0; c < TDIM; ++c)
            acc[r][c] = 0ULL;

    for (int c = 0; c < NCHUNK; ++c) {
        if (c + 1 < NCHUNK) {
            issue_chunk(c + 1, (c + 1) & 1);
            cp_commit();
            cp_wait<1>();          // chunk c fully staged (this thread's view)
        } else {
            cp_wait<0>();
        }
        __syncthreads();           // make all threads' stages + padding zeros visible

        const ulonglong2* Bf = smem + (c & 1) * QPC * VP;
#pragma unroll
        for (int kq = 0; kq < QPC; ++kq) {
            const ulonglong2* p = Bf + kq * VP + lane * RSTRIDE;
            ulonglong2 av[TDIM], bv[TDIM];
#pragma unroll
            for (int r = 0; r < TDIM; ++r) av[r] = p[ti * TDIM + r];
            if (ti == tj) {                 // warp-uniform (warp == tile)
#pragma unroll
                for (int r = 0; r < TDIM; ++r) bv[r] = av[r];
            } else {
#pragma unroll
                for (int r = 0; r < TDIM; ++r) bv[r] = p[tj * TDIM + r];
            }
#pragma unroll
            for (int r = 0; r < TDIM; ++r)
#pragma unroll
                for (int c2 = 0; c2 < TDIM; ++c2) {
                    acc[r][c2] = ffma2(av[r].x, bv[c2].x, acc[r][c2]);
                    acc[r][c2] = ffma2(av[r].y, bv[c2].y, acc[r][c2]);
                }
        }
        __syncthreads();           // protect buffer (c&1) before chunk c+2 overwrites
    }

    // ---- epilogue: fold packed accumulators into smem, then coalesced store ----
    // smem is dead after the last barrier; 32 samples * 351 floats = 44.9 KB fits.
    float* sred = reinterpret_cast<float*>(smem);
    {
#pragma unroll
        for (int r = 0; r < TDIM; ++r) {
            int i = ti * TDIM + r;
            if (i >= FEAT) continue;
#pragma unroll
            for (int c2 = 0; c2 < TDIM; ++c2) {
                int j = tj * TDIM + c2;
                if (j >= FEAT || j <= i) continue;
                unsigned long long u = acc[r][c2];
                float lo = __uint_as_float((unsigned)(u & 0xffffffffULL));
                float hi = __uint_as_float((unsigned)(u >> 32));
                int p = i * (FEAT - 1) - (i * (i - 1)) / 2 + (j - i - 1);
                sred[lane * NPAIR + p] = lo + hi;   // 351%32=31 -> conflict-free
            }
        }
    }
    __syncthreads();

    for (int idx = tid; idx < S_PER_CTA * NPAIR; idx += NTHREADS) {
        int s = idx / NPAIR;
        int p = idx - s * NPAIR;
        out[(size_t)(b0 + s) * OUTW + EMB + p] = sred[idx];
    }
}

extern "C" void kernel_launch(void* const* d_in, const int* in_sizes, int n_in,
                              void* d_out, int out_size) {
    const float* dense  = (const float*)d_in[0];   // [16384, 128]
    const float* sparse = (const float*)d_in[1];   // [16384, 26, 128]
    float* out = (float*)d_out;                    // [16384, 479]

    cudaFuncSetAttribute(interaction_kernel,
                         cudaFuncAttributeMaxDynamicSharedMemorySize, SMEM_BYTES);

    interaction_kernel<<<BATCH_N / S_PER_CTA, NTHREADS, SMEM_BYTES>>>(dense, sparse, out);
}

// round 7
// speedup vs baseline: 1.2206x; 1.2206x over previous
#include <cuda_runtime.h>
#include <cstdint>

#define BATCH_N   16384
#define FEAT      27          // 1 dense + 26 sparse
#define EMB       128
#define S_PER_CTA 16
#define NTHREADS  320         // 10 warps = 10 upper 7x7 tiles
#define TDIM      7           // 28 = 4*7 padded rows
#define RQ        16          // row stride (quads): one 16-quad (256 B) segment per (row, k-half)
#define SQ        450         // sample stride (quads), 28*16=448 -> +2  (== 2 mod 8)
#define HQ        7201        // k-half stride (quads), 16*450=7200 -> +1 (== 1 mod 8)
#define NQUADS    14402
#define SMEM_BYTES (NQUADS * 16)   // 230,432 B  (<= 232,448 B sm_103a opt-in cap)
#define NPAIR     351
#define OUTW      479
#define NCHUNK    8           // k staged as 8 groups of 2 quads per half
#define QPCHUNK   1728        // quads per chunk: 2 kh * 16 s * 27 r * 2 kkl
#define STG_ITERS 6

// Layout: quad index Q = kh*HQ + s*SQ + r*RQ + kk,  kk in [0,16) per half.
// Lane = s*2 + kh; thread reads all kk of its k-half (global k-quad = kh*16+kk).
// Bank phases (8 lanes): (s*SQ + kh*HQ) mod 8 = (2s + kh) + const -> all distinct.

static __device__ const int TI_TAB[10] = {0,0,0,0,1,1,1,2,2,3};
static __device__ const int TJ_TAB[10] = {0,1,2,3,1,2,3,2,3,3};

__device__ __forceinline__ unsigned long long ffma2(unsigned long long a,
                                                    unsigned long long b,
                                                    unsigned long long c) {
    unsigned long long d;
    asm("fma.rn.f32x2 %0, %1, %2, %3;" : "=l"(d) : "l"(a), "l"(b), "l"(c));
    return d;
}
__device__ __forceinline__ void cp_async16(uint32_t smem_addr, const void* gmem) {
    asm volatile("cp.async.cg.shared.global [%0], [%1], 16;" :: "r"(smem_addr), "l"(gmem));
}
__device__ __forceinline__ void cp_commit() {
    asm volatile("cp.async.commit_group;");
}
template <int N>
__device__ __forceinline__ void cp_wait() {
    asm volatile("cp.async.wait_group %0;" :: "n"(N));
}

__global__ void __launch_bounds__(NTHREADS, 1)
interaction_kernel(const float* __restrict__ dense,
                   const float* __restrict__ sparse,
                   float* __restrict__ out) {
    extern __shared__ ulonglong2 smem[];

    const int tid  = threadIdx.x;
    const int warp = tid >> 5;
    const int lane = tid & 31;
    const int b0   = blockIdx.x * S_PER_CTA;
    const uint32_t smem_base = (uint32_t)__cvta_generic_to_shared(smem);

    // ---- per-thread staging descriptors (fixed across chunks) ----
    // chunk c stages, for every (kh,s,r), quads kk = {2c, 2c+1}:
    //   gmem advances 8 floats/chunk, smem advances 2 quads (32 B)/chunk.
    const float* g0[STG_ITERS];
    uint32_t     d0[STG_ITERS];
    bool         act[STG_ITERS];
#pragma unroll
    for (int it = 0; it < STG_ITERS; ++it) {
        int idx = tid + it * NTHREADS;
        act[it] = (idx < QPCHUNK);
        int i2   = act[it] ? idx : 0;
        int kkl  = i2 & 1;
        int rest = i2 >> 1;            // 0..863
        int r    = rest % FEAT;
        int t    = rest / FEAT;        // 0..31
        int s    = t & 15;
        int kh   = t >> 4;
        int b    = b0 + s;
        const float* src = (r == 0)
            ? dense  + (size_t)b * EMB
            : sparse + ((size_t)b * (FEAT - 1) + (r - 1)) * EMB;
        g0[it] = src + (kh * 16 + kkl) * 4;
        d0[it] = smem_base + (uint32_t)((kh * HQ + s * SQ + r * RQ + kkl) * 16);
    }

    // ---- issue ALL 8 chunk groups up-front: max MLP, zero mid-loop issue ----
#pragma unroll
    for (int c = 0; c < NCHUNK; ++c) {
#pragma unroll
        for (int it = 0; it < STG_ITERS; ++it)
            if (act[it]) cp_async16(d0[it] + c * 32, g0[it] + c * 8);
        cp_commit();
    }

    // ---- zero padding row r=27 (never written by cp.async) ----
    for (int idx = tid; idx < 2 * 16 * 16; idx += NTHREADS) {
        int kk = idx & 15;
        int s  = (idx >> 4) & 15;
        int kh = idx >> 8;
        smem[kh * HQ + s * SQ + FEAT * RQ + kk] = make_ulonglong2(0ULL, 0ULL);
    }

    // ---- dense passthrough (overlaps in-flight staging) ----
    for (int idx = tid; idx < S_PER_CTA * EMB; idx += NTHREADS) {
        int s = idx >> 7;
        int d = idx & (EMB - 1);
        out[(size_t)(b0 + s) * OUTW + d] = dense[(size_t)(b0 + s) * EMB + d];
    }

    const int ti = TI_TAB[warp];
    const int tj = TJ_TAB[warp];
    const int s  = lane >> 1;
    const int kh = lane & 1;

    unsigned long long acc[TDIM][TDIM];
#pragma unroll
    for (int r = 0; r < TDIM; ++r)
#pragma unroll
        for (int c = 0; c < TDIM; ++c)
            acc[r][c] = 0ULL;

    const ulonglong2* tb = smem + kh * HQ + s * SQ;

    // ---- mainloop: one wait + one barrier per chunk, pure LDS+FFMA2 after ----
#pragma unroll
    for (int c = 0; c < NCHUNK; ++c) {
        switch (c) {
            case 0: cp_wait<7>(); break;  case 1: cp_wait<6>(); break;
            case 2: cp_wait<5>(); break;  case 3: cp_wait<4>(); break;
            case 4: cp_wait<3>(); break;  case 5: cp_wait<2>(); break;
            case 6: cp_wait<1>(); break;  default: cp_wait<0>(); break;
        }
        __syncthreads();
#pragma unroll
        for (int kkl = 0; kkl < 2; ++kkl) {
            const ulonglong2* p = tb + (2 * c + kkl);
            ulonglong2 av[TDIM], bv[TDIM];
#pragma unroll
            for (int r = 0; r < TDIM; ++r) av[r] = p[(ti * TDIM + r) * RQ];
            if (ti == tj) {                 // warp-uniform
#pragma unroll
                for (int r = 0; r < TDIM; ++r) bv[r] = av[r];
            } else {
#pragma unroll
                for (int r = 0; r < TDIM; ++r) bv[r] = p[(tj * TDIM + r) * RQ];
            }
#pragma unroll
            for (int r = 0; r < TDIM; ++r)
#pragma unroll
                for (int c2 = 0; c2 < TDIM; ++c2) {
                    acc[r][c2] = ffma2(av[r].x, bv[c2].x, acc[r][c2]);
                    acc[r][c2] = ffma2(av[r].y, bv[c2].y, acc[r][c2]);
                }
        }
    }

    __syncthreads();   // all reads of the K-resident buffer complete; smem reusable

    // ---- epilogue: fold f32x2, reduce k-halves via shfl, stage, coalesced store ----
    float* sred = reinterpret_cast<float*>(smem);   // 16*351*4 = 22.5 KB
#pragma unroll
    for (int r = 0; r < TDIM; ++r) {
        int i = ti * TDIM + r;
        if (i >= FEAT) continue;                    // warp-uniform guards
#pragma unroll
        for (int c2 = 0; c2 < TDIM; ++c2) {
            int j = tj * TDIM + c2;
            if (j >= FEAT || j <= i) continue;
            unsigned long long u = acc[r][c2];
            float v = __uint_as_float((unsigned)(u & 0xffffffffULL)) +
                      __uint_as_float((unsigned)(u >> 32));
            v += __shfl_xor_sync(0xffffffffu, v, 1);   // fold the 2 k-halves
            if (kh == 0) {
                int p = i * (FEAT - 1) - (i * (i - 1)) / 2 + (j - i - 1);
                sred[s * NPAIR + p] = v;               // 351%32=31 -> conflict-free
            }
        }
    }
    __syncthreads();

    for (int idx = tid; idx < S_PER_CTA * NPAIR; idx += NTHREADS) {
        int ss = idx / NPAIR;
        int pp = idx - ss * NPAIR;
        out[(size_t)(b0 + ss) * OUTW + EMB + pp] = sred[idx];
    }
}

extern "C" void kernel_launch(void* const* d_in, const int* in_sizes, int n_in,
                              void* d_out, int out_size) {
    // Disambiguate input order by element count (robust to metadata ordering):
    //   dense  = 16384*128      = 2,097,152
    //   sparse = 16384*26*128   = 54,525,952
    const float* dense  = (const float*)d_in[0];
    const float* sparse = (const float*)d_in[1];
    if (n_in >= 2 && in_sizes[0] > in_sizes[1]) {
        dense  = (const float*)d_in[1];
        sparse = (const float*)d_in[0];
    }
    float* out = (float*)d_out;                    // [16384, 479]

    cudaFuncSetAttribute(interaction_kernel,
                         cudaFuncAttributeMaxDynamicSharedMemorySize, SMEM_BYTES);

    interaction_kernel<<<BATCH_N / S_PER_CTA, NTHREADS, SMEM_BYTES>>>(dense, sparse, out);
}